// round 12
// baseline (speedup 1.0000x reference)
#include <cuda_runtime.h>
#include <cuda_fp16.h>
#include <mma.h>
#include <math.h>

using namespace nvcuda;

#define NN   50000
#define NE   800000
#define ET   850000
#define FIN  128
#define HID  64
#define NG   512
#define SLOPE 0.2f
#define PRE_BLOCKS 512
#define NCHUNK 196   // ceil(NN/256)

// ---------------- scratch ----------------
__device__ __half g_hhA[NN * HID];
__device__ __half g_hhB[NN * HID];
__device__ float g_asrcA[NN], g_asrcB[NN];
__device__ float g_adstA[NN], g_adstB[NN];
__device__ int   g_cnt[NN];           // ZERO at rest; s12 resets after use
__device__ int   g_rofs[NN];
__device__ int   g_pos[NN];
__device__ unsigned g_edge[ET];       // src u16 | eatt fp16
__device__ float g_pooled[NG * HID];
__device__ float g_gcnt[NG];
__device__ float g_scal[8];
__device__ int   g_bsum[256];
__device__ int   g_bpre[256];
__device__ float g_part[PRE_BLOCKS];
__device__ unsigned g_s1done;

// ---------------- k_pre ----------------
__global__ void k_pre(const float* __restrict__ We0, const float* __restrict__ ae0,
                      const float* __restrict__ We1, const float* __restrict__ ae1,
                      const float* __restrict__ We2, const float* __restrict__ ae2,
                      const float* __restrict__ ew) {
    __shared__ float sm[256];
    int b = blockIdx.x, t = threadIdx.x;
    int i = b * 256 + t;
    if (i < NG * HID) g_pooled[i] = 0.f;
    if (i < NG) g_gcnt[i] = 0.f;

    float acc = 0.f;
    for (int idx = i; idx < NE; idx += PRE_BLOCKS * 256) acc += ew[idx];
    sm[t] = acc;
    __syncthreads();
    for (int off = 128; off > 0; off >>= 1) {
        if (t < off) sm[t] += sm[t + off];
        __syncthreads();
    }
    if (t == 0) g_part[b] = sm[0];
    __syncthreads();

    if (b < 3) {
        const float* We = (b == 0) ? We0 : (b == 1) ? We1 : We2;
        const float* ae = (b == 0) ? ae0 : (b == 1) ? ae1 : ae2;
        sm[t] = (t < HID) ? We[t] * ae[t] : 0.f;
        __syncthreads();
        for (int off = 128; off > 0; off >>= 1) {
            if (t < off) sm[t] += sm[t + off];
            __syncthreads();
        }
        if (t == 0) g_scal[1 + b] = sm[0];
    }
}

__global__ void k_hist(const int* __restrict__ eidx) {
    int q = blockIdx.x * blockDim.x + threadIdx.x;
    if (q >= NE / 4) return;
    int4 d4 = reinterpret_cast<const int4*>(eidx + NE)[q];
    atomicAdd(&g_cnt[d4.x], 1);
    atomicAdd(&g_cnt[d4.y], 1);
    atomicAdd(&g_cnt[d4.z], 1);
    atomicAdd(&g_cnt[d4.w], 1);
}

// warp-shuffle 256-scan helper: returns INCLUSIVE scan of v across the block.
__device__ __forceinline__ int block_incl_scan256(int v, int t, int* wsum) {
    int lane = t & 31, w = t >> 5;
    int x = v;
    #pragma unroll
    for (int off = 1; off < 32; off <<= 1) {
        int y = __shfl_up_sync(0xffffffffu, x, off);
        if (lane >= off) x += y;
    }
    if (lane == 31) wsum[w] = x;
    __syncthreads();
    if (w == 0) {
        int s = (lane < 8) ? wsum[lane] : 0;
        #pragma unroll
        for (int off = 1; off < 8; off <<= 1) {
            int y = __shfl_up_sync(0xffffffffu, s, off);
            if (lane >= off) s += y;
        }
        if (lane < 8) wsum[lane] = s;
    }
    __syncthreads();
    if (w > 0) x += wsum[w - 1];
    return x;
}

// fused: local scans (+self-loop +1, reset cnt) ; last block scans block sums
// and finalizes edge-weight total. Grid MUST be NCHUNK.
__global__ void k_s12() {
    __shared__ int wsum[8];
    __shared__ int s_last;
    int t = threadIdx.x;
    int i = blockIdx.x * 256 + t;
    int v = 0;
    if (i < NN) {
        v = g_cnt[i] + 1;      // fold self-loop
        g_cnt[i] = 0;          // reset for next replay
    }
    int incl = block_incl_scan256(v, t, wsum);
    if (i < NN) {
        int r = incl - v;
        g_rofs[i] = r;
        g_pos[i] = r;
    }
    if (t == 255) g_bsum[blockIdx.x] = incl;
    __threadfence();
    __syncthreads();
    if (t == 0) {
        unsigned done = atomicAdd(&g_s1done, 1u);
        s_last = (done == (unsigned)gridDim.x - 1u);
    }
    __syncthreads();
    if (!s_last) return;

    // ---- last block: scan block sums + ew total ----
    if (t == 0) g_s1done = 0;
    __syncthreads();
    int bv = (t < NCHUNK) ? g_bsum[t] : 0;
    int bincl = block_incl_scan256(bv, t, wsum);
    if (t < NCHUNK) g_bpre[t] = bincl - bv;
    __syncthreads();
    __shared__ float sf[256];
    sf[t] = g_part[t] + g_part[t + 256];
    __syncthreads();
    for (int off = 128; off > 0; off >>= 1) {
        if (t < off) sf[t] += sf[t + off];
        __syncthreads();
    }
    if (t == 0) g_scal[0] = sf[0];
}

__global__ void k_scat(const int* __restrict__ eidx, const float* __restrict__ ew) {
    int e = blockIdx.x * blockDim.x + threadIdx.x;
    if (e >= ET) return;
    int s, d;
    float a;
    if (e < NE) {
        s = eidx[e];
        d = eidx[NE + e];
        a = ew[e];
    } else {
        s = d = e - NE;
        a = g_scal[0] * (1.0f / (float)NE);
    }
    int p = atomicAdd(&g_pos[d], 1) + g_bpre[d >> 8];
    g_edge[p] = (unsigned)s |
                ((unsigned)__half_as_ushort(__float2half_rn(a)) << 16);
}

// ---------------- per-warp segment aggregation core (templated unroll) ----------
template <int U>
__device__ __forceinline__ void agg_node(int n, int lane, float c,
                                         const __half* __restrict__ hh_in,
                                         const float* __restrict__ asrc_in,
                                         float adstn,
                                         float& ox, float& oy) {
    int start = g_rofs[n] + g_bpre[n >> 8];
    int n2 = n + 1;
    int end = (n2 == NN) ? ET : g_rofs[n2] + g_bpre[n2 >> 8];
    float accx = 0.f, accy = 0.f, ssum = 0.f;

    for (int base = start; base < end; base += 32) {
        int i = base + lane;
        int s_l = 0;
        float alpha = 0.f;
        if (i < end) {
            unsigned ev = g_edge[i];
            s_l = (int)(ev & 0xFFFFu);
            float ea = __half2float(__ushort_as_half((unsigned short)(ev >> 16)));
            float al = asrc_in[s_l] + adstn + ea * c;
            al = fmaxf(al, 0.f) + SLOPE * fminf(al, 0.f);
            alpha = __expf(al);
        }
        ssum += alpha;
        int cnt = min(32, end - base);
        int jj = 0;
        for (; jj + U <= cnt; jj += U) {
            __half2 hv[U];
            float aj[U];
            #pragma unroll
            for (int u = 0; u < U; u++) {
                int sj = __shfl_sync(0xffffffffu, s_l, jj + u);
                aj[u]  = __shfl_sync(0xffffffffu, alpha, jj + u);
                hv[u] = *reinterpret_cast<const __half2*>(
                    &hh_in[((size_t)sj << 6) + (lane << 1)]);
            }
            #pragma unroll
            for (int u = 0; u < U; u++) {
                float2 f = __half22float2(hv[u]);
                accx = fmaf(aj[u], f.x, accx);
                accy = fmaf(aj[u], f.y, accy);
            }
        }
        for (; jj < cnt; jj++) {
            int   sj = __shfl_sync(0xffffffffu, s_l, jj);
            float a2 = __shfl_sync(0xffffffffu, alpha, jj);
            float2 f = __half22float2(*reinterpret_cast<const __half2*>(
                &hh_in[((size_t)sj << 6) + (lane << 1)]));
            accx = fmaf(a2, f.x, accx);
            accy = fmaf(a2, f.y, accy);
        }
    }
    #pragma unroll
    for (int off = 16; off > 0; off >>= 1)
        ssum += __shfl_xor_sync(0xffffffffu, ssum, off);
    float inv = 1.f / (ssum + 1e-16f);
    ox = accx * inv;
    oy = accy * inv;
}

// ---------------- layer-1 GEMM (ext input) + logits -> A set ----------------
#define LDA 136
#define LDB 72
#define LDC 68

__global__ void k_gemm1(const float* __restrict__ X, const float* __restrict__ W,
                        const float* __restrict__ as_, const float* __restrict__ ad_) {
    __shared__ __align__(16) char sbuf[18432 + 17408];
    __half* Bs = reinterpret_cast<__half*>(sbuf);
    __half* As = reinterpret_cast<__half*>(sbuf + 18432);
    float*  Cs = reinterpret_cast<float*>(sbuf + 18432);

    int t = threadIdx.x;
    int w = t >> 5;
    int n0 = blockIdx.x * 64;

    {
        int r = t >> 1;
        int n = n0 + r;
        const float4* xrow = reinterpret_cast<const float4*>(X + (size_t)n * FIN);
        #pragma unroll
        for (int f = 0; f < 16; f++) {
            int c4 = (t & 1) * 16 + f;
            float4 v = (n < NN) ? xrow[c4] : make_float4(0, 0, 0, 0);
            __half2* p = reinterpret_cast<__half2*>(&As[r * LDA + c4 * 4]);
            p[0] = __floats2half2_rn(v.x, v.y);
            p[1] = __floats2half2_rn(v.z, v.w);
        }
        const float4* w4 = reinterpret_cast<const float4*>(W);
        for (int idx = t; idx < FIN * HID / 4; idx += 128) {
            int rr = idx >> 4, c4 = idx & 15;
            float4 v = w4[idx];
            __half2* p = reinterpret_cast<__half2*>(&Bs[rr * LDB + c4 * 4]);
            p[0] = __floats2half2_rn(v.x, v.y);
            p[1] = __floats2half2_rn(v.z, v.w);
        }
    }
    __syncthreads();

    wmma::fragment<wmma::accumulator, 16, 16, 16, float> acc[4];
    #pragma unroll
    for (int nt = 0; nt < 4; nt++) wmma::fill_fragment(acc[nt], 0.f);
    for (int kt = 0; kt < FIN / 16; kt++) {
        wmma::fragment<wmma::matrix_a, 16, 16, 16, __half, wmma::row_major> af;
        wmma::load_matrix_sync(af, &As[(w * 16) * LDA + kt * 16], LDA);
        #pragma unroll
        for (int nt = 0; nt < 4; nt++) {
            wmma::fragment<wmma::matrix_b, 16, 16, 16, __half, wmma::row_major> bf;
            wmma::load_matrix_sync(bf, &Bs[(kt * 16) * LDB + nt * 16], LDB);
            wmma::mma_sync(acc[nt], af, bf, acc[nt]);
        }
    }
    __syncthreads();
    #pragma unroll
    for (int nt = 0; nt < 4; nt++)
        wmma::store_matrix_sync(&Cs[(w * 16) * LDC + nt * 16], acc[nt], LDC,
                                wmma::mem_row_major);
    __syncthreads();

    {
        int r = t >> 1;
        int n = n0 + r;
        int cbase = (t & 1) * 32;
        float s = 0.f, d = 0.f;
        if (n < NN) {
            #pragma unroll
            for (int c = 0; c < 32; c += 2) {
                int col = cbase + c;
                float v0 = Cs[r * LDC + col];
                float v1 = Cs[r * LDC + col + 1];
                *reinterpret_cast<__half2*>(&g_hhA[((size_t)n << 6) + col]) =
                    __floats2half2_rn(v0, v1);
                s = fmaf(v0, as_[col], s); s = fmaf(v1, as_[col + 1], s);
                d = fmaf(v0, ad_[col], d); d = fmaf(v1, ad_[col + 1], d);
            }
        }
        s += __shfl_xor_sync(0xffffffffu, s, 1);
        d += __shfl_xor_sync(0xffffffffu, d, 1);
        if ((t & 1) == 0 && n < NN) {
            g_asrcA[n] = s;
            g_adstA[n] = d;
        }
    }
}

// ---------------- FUSED agg + GEMM (HID->HID) + logits ----------------
// 512 threads, 2 blocks/SM forced (<=64 regs) to keep the gather phase
// occupancy-fed. Warp w aggregates nodes n0+4w..n0+4w+3 into As.
__global__ void __launch_bounds__(512, 2) k_agge(
    int layer,
    const __half* __restrict__ hh_in, const float* __restrict__ asrc_in,
    const float* __restrict__ adst_in,
    __half* __restrict__ hh_out, float* __restrict__ asrc_out,
    float* __restrict__ adst_out,
    const float* __restrict__ W, const float* __restrict__ bias_prev,
    const float* __restrict__ as_, const float* __restrict__ ad_) {
    __shared__ __align__(16) char sbuf[9216 + 17408];   // Bs[64][72] + As[64][136]
    __half* Bs = reinterpret_cast<__half*>(sbuf);
    __half* As = reinterpret_cast<__half*>(sbuf + 9216);
    float*  Cs = reinterpret_cast<float*>(sbuf);        // [64][68] alias (post-MMA)

    int t = threadIdx.x;
    int w = t >> 5;
    int lane = t & 31;
    int n0 = blockIdx.x * 64;
    float c = g_scal[1 + layer];
    float b0v = bias_prev[lane << 1];
    float b1v = bias_prev[(lane << 1) + 1];

    {
        const float4* w4 = reinterpret_cast<const float4*>(W);
        for (int idx = t; idx < HID * HID / 4; idx += 512) {
            int rr = idx >> 4, c4 = idx & 15;
            float4 v = w4[idx];
            __half2* p = reinterpret_cast<__half2*>(&Bs[rr * LDB + c4 * 4]);
            p[0] = __floats2half2_rn(v.x, v.y);
            p[1] = __floats2half2_rn(v.z, v.w);
        }
    }

    #pragma unroll
    for (int m = 0; m < 4; m++) {
        int r = w * 4 + m;
        int n = n0 + r;
        float ox = 0.f, oy = 0.f;
        if (n < NN)
            agg_node<4>(n, lane, c, hh_in, asrc_in, adst_in[n], ox, oy);
        ox = fmaxf(ox + b0v, 0.f);
        oy = fmaxf(oy + b1v, 0.f);
        *reinterpret_cast<__half2*>(&As[r * LDA + (lane << 1)]) =
            __floats2half2_rn(ox, oy);
    }
    __syncthreads();

    int rt = w >> 2, ct = w & 3;
    wmma::fragment<wmma::accumulator, 16, 16, 16, float> acc;
    wmma::fill_fragment(acc, 0.f);
    #pragma unroll
    for (int kt = 0; kt < HID / 16; kt++) {
        wmma::fragment<wmma::matrix_a, 16, 16, 16, __half, wmma::row_major> af;
        wmma::fragment<wmma::matrix_b, 16, 16, 16, __half, wmma::row_major> bf;
        wmma::load_matrix_sync(af, &As[(rt * 16) * LDA + kt * 16], LDA);
        wmma::load_matrix_sync(bf, &Bs[(kt * 16) * LDB + ct * 16], LDB);
        wmma::mma_sync(acc, af, bf, acc);
    }
    __syncthreads();
    wmma::store_matrix_sync(&Cs[(rt * 16) * LDC + ct * 16], acc, LDC,
                            wmma::mem_row_major);
    __syncthreads();

    {
        int r = t >> 3;
        int n = n0 + r;
        int cbase = (t & 7) * 8;
        float s = 0.f, d = 0.f;
        if (n < NN) {
            #pragma unroll
            for (int cc = 0; cc < 8; cc += 2) {
                int col = cbase + cc;
                float v0 = Cs[r * LDC + col];
                float v1 = Cs[r * LDC + col + 1];
                *reinterpret_cast<__half2*>(&hh_out[((size_t)n << 6) + col]) =
                    __floats2half2_rn(v0, v1);
                s = fmaf(v0, as_[col], s); s = fmaf(v1, as_[col + 1], s);
                d = fmaf(v0, ad_[col], d); d = fmaf(v1, ad_[col + 1], d);
            }
        }
        #pragma unroll
        for (int off = 4; off > 0; off >>= 1) {
            s += __shfl_down_sync(0xffffffffu, s, off, 8);
            d += __shfl_down_sync(0xffffffffu, d, off, 8);
        }
        if ((t & 7) == 0 && n < NN) {
            asrc_out[n] = s;
            adst_out[n] = d;
        }
    }
}

// ---------------- final agg (layer 2) + pooling ----------------
__global__ void k_aggp(const int* __restrict__ batch,
                       const float* __restrict__ bias_last) {
    int n = blockIdx.x * 8 + (threadIdx.x >> 5);
    int lane = threadIdx.x & 31;
    float c = g_scal[3];
    float ox, oy;
    agg_node<8>(n, lane, c, g_hhA, g_asrcA, g_adstA[n], ox, oy);
    int g = batch[n];
    float2 bb = *reinterpret_cast<const float2*>(&bias_last[lane << 1]);
    float* p = &g_pooled[((size_t)g << 6) + (lane << 1)];
    asm volatile("red.global.add.v2.f32 [%0], {%1,%2};"
                 :: "l"(p), "f"(ox + bb.x), "f"(oy + bb.y) : "memory");
    if (lane == 0) atomicAdd(&g_gcnt[g], 1.f);
}

// ---------------- readout ----------------
__global__ void k_read(const float* __restrict__ lin_w,
                       const float* __restrict__ lin_b, float* __restrict__ outp) {
    __shared__ float r[64];
    int g = blockIdx.x, j = threadIdx.x;
    float cnt = fmaxf(g_gcnt[g], 1.f);
    r[j] = (g_pooled[(size_t)g * HID + j] / cnt) * lin_w[j];
    __syncthreads();
    for (int off = 32; off > 0; off >>= 1) {
        if (j < off) r[j] += r[j + off];
        __syncthreads();
    }
    if (j == 0) {
        float v = r[0] + lin_b[0];
        outp[g] = 1.f / (1.f + expf(-v));
    }
}

// ---------------- stream/event resources (static init) ----------------
static cudaStream_t g_stream2;
static cudaEvent_t  g_evFork, g_evGemm1, g_evPre;
namespace {
struct InitRes {
    InitRes() {
        cudaStreamCreateWithFlags(&g_stream2, cudaStreamNonBlocking);
        cudaEventCreateWithFlags(&g_evFork,  cudaEventDisableTiming);
        cudaEventCreateWithFlags(&g_evGemm1, cudaEventDisableTiming);
        cudaEventCreateWithFlags(&g_evPre,   cudaEventDisableTiming);
    }
};
InitRes g_initres;
}

// ---------------- launch ----------------
extern "C" void kernel_launch(void* const* d_in, const int* in_sizes, int n_in,
                              void* d_out, int out_size) {
    const float* x     = (const float*)d_in[0];
    const int*   eidx  = (const int*)  d_in[1];
    const float* ew    = (const float*)d_in[2];
    const int*   batch = (const int*)  d_in[3];
    const float* W[3]  = {(const float*)d_in[4],  (const float*)d_in[10], (const float*)d_in[16]};
    const float* as_[3]= {(const float*)d_in[5],  (const float*)d_in[11], (const float*)d_in[17]};
    const float* ad_[3]= {(const float*)d_in[6],  (const float*)d_in[12], (const float*)d_in[18]};
    const float* We[3] = {(const float*)d_in[7],  (const float*)d_in[13], (const float*)d_in[19]};
    const float* ae[3] = {(const float*)d_in[8],  (const float*)d_in[14], (const float*)d_in[20]};
    const float* b[3]  = {(const float*)d_in[9],  (const float*)d_in[15], (const float*)d_in[21]};
    const float* lin_w = (const float*)d_in[22];
    const float* lin_b = (const float*)d_in[23];
    float* outp = (float*)d_out;

    const int TILE_BLOCKS = (NN + 63) / 64;   // 782
    const int WARP_BLOCKS = NN / 8;           // 6250

    __half *hhA = nullptr, *hhB = nullptr;
    float *asA = nullptr, *asB = nullptr, *adA = nullptr, *adB = nullptr;
    cudaGetSymbolAddress((void**)&hhA, g_hhA);
    cudaGetSymbolAddress((void**)&hhB, g_hhB);
    cudaGetSymbolAddress((void**)&asA, g_asrcA);
    cudaGetSymbolAddress((void**)&asB, g_asrcB);
    cudaGetSymbolAddress((void**)&adA, g_adstA);
    cudaGetSymbolAddress((void**)&adB, g_adstB);

    // fork stream2: pre first (unblocks scan), then gemm1
    cudaEventRecord(g_evFork, 0);
    cudaStreamWaitEvent(g_stream2, g_evFork, 0);
    k_pre<<<PRE_BLOCKS, 256, 0, g_stream2>>>(We[0], ae[0], We[1], ae[1],
                                             We[2], ae[2], ew);
    cudaEventRecord(g_evPre, g_stream2);
    k_gemm1<<<TILE_BLOCKS, 128, 0, g_stream2>>>(x, W[0], as_[0], ad_[0]);
    cudaEventRecord(g_evGemm1, g_stream2);

    // capture stream: hist immediately, then scan (needs pre), scat
    k_hist<<<(NE / 4 + 255) / 256, 256>>>(eidx);
    cudaStreamWaitEvent(0, g_evPre, 0);
    k_s12<<<NCHUNK, 256>>>();
    k_scat<<<(ET + 255) / 256, 256>>>(eidx, ew);

    cudaStreamWaitEvent(0, g_evGemm1, 0);
    k_agge<<<TILE_BLOCKS, 512>>>(0, hhA, asA, adA, hhB, asB, adB,
                                 W[1], b[0], as_[1], ad_[1]);
    k_agge<<<TILE_BLOCKS, 512>>>(1, hhB, asB, adB, hhA, asA, adA,
                                 W[2], b[1], as_[2], ad_[2]);
    k_aggp<<<WARP_BLOCKS, 256>>>(batch, b[2]);
    k_read<<<NG, 64>>>(lin_w, lin_b, outp);
}

// round 13
// speedup vs baseline: 1.0298x; 1.0298x over previous
#include <cuda_runtime.h>
#include <cuda_fp16.h>
#include <mma.h>
#include <math.h>

using namespace nvcuda;

#define NN   50000
#define NE   800000
#define ET   850000
#define FIN  128
#define HID  64
#define NG   512
#define SLOPE 0.2f
#define PRE_BLOCKS 512
#define NCHUNK 196   // ceil(NN/256)

// ---------------- scratch ----------------
__device__ __half g_hhA[NN * HID];
__device__ __half g_hhB[NN * HID];
__device__ float g_asrcA[NN], g_asrcB[NN];
__device__ float g_adstA[NN], g_adstB[NN];
__device__ int   g_cnt[NN];           // ZERO at rest; s12 resets after use
__device__ int   g_rofs[NN];
__device__ int   g_pos[NN];
__device__ unsigned g_edge[ET];       // src u16 | eatt fp16
__device__ float g_pooled[NG * HID];
__device__ float g_gcnt[NG];
__device__ float g_scal[8];
__device__ int   g_bsum[256];
__device__ int   g_bpre[256];
__device__ float g_part[PRE_BLOCKS];
__device__ unsigned g_s1done;

// ---------------- k_pre ----------------
__global__ void k_pre(const float* __restrict__ We0, const float* __restrict__ ae0,
                      const float* __restrict__ We1, const float* __restrict__ ae1,
                      const float* __restrict__ We2, const float* __restrict__ ae2,
                      const float* __restrict__ ew) {
    __shared__ float sm[256];
    int b = blockIdx.x, t = threadIdx.x;
    int i = b * 256 + t;
    if (i < NG * HID) g_pooled[i] = 0.f;
    if (i < NG) g_gcnt[i] = 0.f;

    float acc = 0.f;
    for (int idx = i; idx < NE; idx += PRE_BLOCKS * 256) acc += ew[idx];
    sm[t] = acc;
    __syncthreads();
    for (int off = 128; off > 0; off >>= 1) {
        if (t < off) sm[t] += sm[t + off];
        __syncthreads();
    }
    if (t == 0) g_part[b] = sm[0];
    __syncthreads();

    if (b < 3) {
        const float* We = (b == 0) ? We0 : (b == 1) ? We1 : We2;
        const float* ae = (b == 0) ? ae0 : (b == 1) ? ae1 : ae2;
        sm[t] = (t < HID) ? We[t] * ae[t] : 0.f;
        __syncthreads();
        for (int off = 128; off > 0; off >>= 1) {
            if (t < off) sm[t] += sm[t + off];
            __syncthreads();
        }
        if (t == 0) g_scal[1 + b] = sm[0];
    }
}

__global__ void k_hist(const int* __restrict__ eidx) {
    int q = blockIdx.x * blockDim.x + threadIdx.x;
    if (q >= NE / 4) return;
    int4 d4 = reinterpret_cast<const int4*>(eidx + NE)[q];
    atomicAdd(&g_cnt[d4.x], 1);
    atomicAdd(&g_cnt[d4.y], 1);
    atomicAdd(&g_cnt[d4.z], 1);
    atomicAdd(&g_cnt[d4.w], 1);
}

// warp-shuffle 256-scan helper: INCLUSIVE scan across the block.
__device__ __forceinline__ int block_incl_scan256(int v, int t, int* wsum) {
    int lane = t & 31, w = t >> 5;
    int x = v;
    #pragma unroll
    for (int off = 1; off < 32; off <<= 1) {
        int y = __shfl_up_sync(0xffffffffu, x, off);
        if (lane >= off) x += y;
    }
    if (lane == 31) wsum[w] = x;
    __syncthreads();
    if (w == 0) {
        int s = (lane < 8) ? wsum[lane] : 0;
        #pragma unroll
        for (int off = 1; off < 8; off <<= 1) {
            int y = __shfl_up_sync(0xffffffffu, s, off);
            if (lane >= off) s += y;
        }
        if (lane < 8) wsum[lane] = s;
    }
    __syncthreads();
    if (w > 0) x += wsum[w - 1];
    return x;
}

// fused local scans + last-block global scan + ew total. Grid MUST be NCHUNK.
__global__ void k_s12() {
    __shared__ int wsum[8];
    __shared__ int s_last;
    int t = threadIdx.x;
    int i = blockIdx.x * 256 + t;
    int v = 0;
    if (i < NN) {
        v = g_cnt[i] + 1;      // fold self-loop
        g_cnt[i] = 0;          // reset for next replay
    }
    int incl = block_incl_scan256(v, t, wsum);
    if (i < NN) {
        int r = incl - v;
        g_rofs[i] = r;
        g_pos[i] = r;
    }
    if (t == 255) g_bsum[blockIdx.x] = incl;
    __threadfence();
    __syncthreads();
    if (t == 0) {
        unsigned done = atomicAdd(&g_s1done, 1u);
        s_last = (done == (unsigned)gridDim.x - 1u);
    }
    __syncthreads();
    if (!s_last) return;

    if (t == 0) g_s1done = 0;
    __syncthreads();
    int bv = (t < NCHUNK) ? g_bsum[t] : 0;
    int bincl = block_incl_scan256(bv, t, wsum);
    if (t < NCHUNK) g_bpre[t] = bincl - bv;
    __syncthreads();
    __shared__ float sf[256];
    sf[t] = g_part[t] + g_part[t + 256];
    __syncthreads();
    for (int off = 128; off > 0; off >>= 1) {
        if (t < off) sf[t] += sf[t + off];
        __syncthreads();
    }
    if (t == 0) g_scal[0] = sf[0];
}

__global__ void k_scat(const int* __restrict__ eidx, const float* __restrict__ ew) {
    int e = blockIdx.x * blockDim.x + threadIdx.x;
    if (e >= ET) return;
    int s, d;
    float a;
    if (e < NE) {
        s = eidx[e];
        d = eidx[NE + e];
        a = ew[e];
    } else {
        s = d = e - NE;
        a = g_scal[0] * (1.0f / (float)NE);
    }
    int p = atomicAdd(&g_pos[d], 1) + g_bpre[d >> 8];
    g_edge[p] = (unsigned)s |
                ((unsigned)__half_as_ushort(__float2half_rn(a)) << 16);
}

// ---------------- per-warp segment aggregation core (general path) ----------
template <int U>
__device__ __forceinline__ void agg_node(int n, int lane, float c,
                                         const __half* __restrict__ hh_in,
                                         const float* __restrict__ asrc_in,
                                         float adstn,
                                         float& ox, float& oy) {
    int start = g_rofs[n] + g_bpre[n >> 8];
    int n2 = n + 1;
    int end = (n2 == NN) ? ET : g_rofs[n2] + g_bpre[n2 >> 8];
    float accx = 0.f, accy = 0.f, ssum = 0.f;

    for (int base = start; base < end; base += 32) {
        int i = base + lane;
        int s_l = 0;
        float alpha = 0.f;
        if (i < end) {
            unsigned ev = g_edge[i];
            s_l = (int)(ev & 0xFFFFu);
            float ea = __half2float(__ushort_as_half((unsigned short)(ev >> 16)));
            float al = asrc_in[s_l] + adstn + ea * c;
            al = fmaxf(al, 0.f) + SLOPE * fminf(al, 0.f);
            alpha = __expf(al);
        }
        ssum += alpha;
        int cnt = min(32, end - base);
        int jj = 0;
        for (; jj + U <= cnt; jj += U) {
            __half2 hv[U];
            float aj[U];
            #pragma unroll
            for (int u = 0; u < U; u++) {
                int sj = __shfl_sync(0xffffffffu, s_l, jj + u);
                aj[u]  = __shfl_sync(0xffffffffu, alpha, jj + u);
                hv[u] = *reinterpret_cast<const __half2*>(
                    &hh_in[((size_t)sj << 6) + (lane << 1)]);
            }
            #pragma unroll
            for (int u = 0; u < U; u++) {
                float2 f = __half22float2(hv[u]);
                accx = fmaf(aj[u], f.x, accx);
                accy = fmaf(aj[u], f.y, accy);
            }
        }
        for (; jj < cnt; jj++) {
            int   sj = __shfl_sync(0xffffffffu, s_l, jj);
            float a2 = __shfl_sync(0xffffffffu, alpha, jj);
            float2 f = __half22float2(*reinterpret_cast<const __half2*>(
                &hh_in[((size_t)sj << 6) + (lane << 1)]));
            accx = fmaf(a2, f.x, accx);
            accy = fmaf(a2, f.y, accy);
        }
    }
    #pragma unroll
    for (int off = 16; off > 0; off >>= 1)
        ssum += __shfl_xor_sync(0xffffffffu, ssum, off);
    float inv = 1.f / (ssum + 1e-16f);
    ox = accx * inv;
    oy = accy * inv;
}

// ---------------- layer-1 GEMM (ext input) + logits -> A set ----------------
#define LDA 136
#define LDB 72
#define LDC 68

__global__ void k_gemm1(const float* __restrict__ X, const float* __restrict__ W,
                        const float* __restrict__ as_, const float* __restrict__ ad_) {
    __shared__ __align__(16) char sbuf[18432 + 17408];
    __half* Bs = reinterpret_cast<__half*>(sbuf);
    __half* As = reinterpret_cast<__half*>(sbuf + 18432);
    float*  Cs = reinterpret_cast<float*>(sbuf + 18432);

    int t = threadIdx.x;
    int w = t >> 5;
    int n0 = blockIdx.x * 64;

    {
        int r = t >> 1;
        int n = n0 + r;
        const float4* xrow = reinterpret_cast<const float4*>(X + (size_t)n * FIN);
        #pragma unroll
        for (int f = 0; f < 16; f++) {
            int c4 = (t & 1) * 16 + f;
            float4 v = (n < NN) ? xrow[c4] : make_float4(0, 0, 0, 0);
            __half2* p = reinterpret_cast<__half2*>(&As[r * LDA + c4 * 4]);
            p[0] = __floats2half2_rn(v.x, v.y);
            p[1] = __floats2half2_rn(v.z, v.w);
        }
        const float4* w4 = reinterpret_cast<const float4*>(W);
        for (int idx = t; idx < FIN * HID / 4; idx += 128) {
            int rr = idx >> 4, c4 = idx & 15;
            float4 v = w4[idx];
            __half2* p = reinterpret_cast<__half2*>(&Bs[rr * LDB + c4 * 4]);
            p[0] = __floats2half2_rn(v.x, v.y);
            p[1] = __floats2half2_rn(v.z, v.w);
        }
    }
    __syncthreads();

    wmma::fragment<wmma::accumulator, 16, 16, 16, float> acc[4];
    #pragma unroll
    for (int nt = 0; nt < 4; nt++) wmma::fill_fragment(acc[nt], 0.f);
    for (int kt = 0; kt < FIN / 16; kt++) {
        wmma::fragment<wmma::matrix_a, 16, 16, 16, __half, wmma::row_major> af;
        wmma::load_matrix_sync(af, &As[(w * 16) * LDA + kt * 16], LDA);
        #pragma unroll
        for (int nt = 0; nt < 4; nt++) {
            wmma::fragment<wmma::matrix_b, 16, 16, 16, __half, wmma::row_major> bf;
            wmma::load_matrix_sync(bf, &Bs[(kt * 16) * LDB + nt * 16], LDB);
            wmma::mma_sync(acc[nt], af, bf, acc[nt]);
        }
    }
    __syncthreads();
    #pragma unroll
    for (int nt = 0; nt < 4; nt++)
        wmma::store_matrix_sync(&Cs[(w * 16) * LDC + nt * 16], acc[nt], LDC,
                                wmma::mem_row_major);
    __syncthreads();

    {
        int r = t >> 1;
        int n = n0 + r;
        int cbase = (t & 1) * 32;
        float s = 0.f, d = 0.f;
        if (n < NN) {
            #pragma unroll
            for (int c = 0; c < 32; c += 2) {
                int col = cbase + c;
                float v0 = Cs[r * LDC + col];
                float v1 = Cs[r * LDC + col + 1];
                *reinterpret_cast<__half2*>(&g_hhA[((size_t)n << 6) + col]) =
                    __floats2half2_rn(v0, v1);
                s = fmaf(v0, as_[col], s); s = fmaf(v1, as_[col + 1], s);
                d = fmaf(v0, ad_[col], d); d = fmaf(v1, ad_[col + 1], d);
            }
        }
        s += __shfl_xor_sync(0xffffffffu, s, 1);
        d += __shfl_xor_sync(0xffffffffu, d, 1);
        if ((t & 1) == 0 && n < NN) {
            g_asrcA[n] = s;
            g_adstA[n] = d;
        }
    }
}

// ---------------- FUSED agg + GEMM (HID->HID) + logits ----------------
// 512 threads, warp w aggregates nodes n0+4w..n0+4w+3 into As.
// Fast path: segments <=32 edges get their alpha chains batched across
// all 4 nodes up-front (4x MLP on the edge->asrc->exp latency chain).
__global__ void __launch_bounds__(512) k_agge(
    int layer,
    const __half* __restrict__ hh_in, const float* __restrict__ asrc_in,
    const float* __restrict__ adst_in,
    __half* __restrict__ hh_out, float* __restrict__ asrc_out,
    float* __restrict__ adst_out,
    const float* __restrict__ W, const float* __restrict__ bias_prev,
    const float* __restrict__ as_, const float* __restrict__ ad_) {
    __shared__ __align__(16) char sbuf[9216 + 17408];   // Bs[64][72] + As[64][136]
    __half* Bs = reinterpret_cast<__half*>(sbuf);
    __half* As = reinterpret_cast<__half*>(sbuf + 9216);
    float*  Cs = reinterpret_cast<float*>(sbuf);        // [64][68] alias (post-MMA)

    int t = threadIdx.x;
    int w = t >> 5;
    int lane = t & 31;
    int n0 = blockIdx.x * 64;
    float c = g_scal[1 + layer];
    float b0v = bias_prev[lane << 1];
    float b1v = bias_prev[(lane << 1) + 1];

    {
        const float4* w4 = reinterpret_cast<const float4*>(W);
        for (int idx = t; idx < HID * HID / 4; idx += 512) {
            int rr = idx >> 4, c4 = idx & 15;
            float4 v = w4[idx];
            __half2* p = reinterpret_cast<__half2*>(&Bs[rr * LDB + c4 * 4]);
            p[0] = __floats2half2_rn(v.x, v.y);
            p[1] = __floats2half2_rn(v.z, v.w);
        }
    }

    // ---- phase 1: segment bounds + batched alpha for fast-path nodes ----
    int starts[4], cnts[4];
    float adv[4];
    #pragma unroll
    for (int m = 0; m < 4; m++) {
        int n = n0 + w * 4 + m;
        int st = 0, en = 0;
        float ad = 0.f;
        if (n < NN) {
            st = g_rofs[n] + g_bpre[n >> 8];
            int n2 = n + 1;
            en = (n2 == NN) ? ET : g_rofs[n2] + g_bpre[n2 >> 8];
            ad = adst_in[n];
        }
        starts[m] = st;
        cnts[m] = en - st;
        adv[m] = ad;
    }

    int   s4[4];
    float al4[4];
    #pragma unroll
    for (int m = 0; m < 4; m++) {
        bool act = (cnts[m] <= 32) && (lane < cnts[m]);
        unsigned ev = act ? g_edge[starts[m] + lane] : 0u;
        int sl = (int)(ev & 0xFFFFu);
        float av = 0.f;
        if (act) {
            float ea = __half2float(__ushort_as_half((unsigned short)(ev >> 16)));
            float al = asrc_in[sl] + adv[m] + ea * c;
            al = fmaxf(al, 0.f) + SLOPE * fminf(al, 0.f);
            av = __expf(al);
        }
        s4[m] = sl;
        al4[m] = av;
    }

    // ---- phase 2: per-node gather + normalize -> As ----
    #pragma unroll
    for (int m = 0; m < 4; m++) {
        int r = w * 4 + m;
        int n = n0 + r;
        float ox = 0.f, oy = 0.f;
        if (n < NN) {
            if (cnts[m] <= 32) {
                float ssum = al4[m];
                #pragma unroll
                for (int off = 16; off > 0; off >>= 1)
                    ssum += __shfl_xor_sync(0xffffffffu, ssum, off);
                float accx = 0.f, accy = 0.f;
                int cnt = cnts[m];
                int jj = 0;
                for (; jj + 8 <= cnt; jj += 8) {
                    __half2 hv[8];
                    float aj[8];
                    #pragma unroll
                    for (int u = 0; u < 8; u++) {
                        int sj = __shfl_sync(0xffffffffu, s4[m], jj + u);
                        aj[u]  = __shfl_sync(0xffffffffu, al4[m], jj + u);
                        hv[u] = *reinterpret_cast<const __half2*>(
                            &hh_in[((size_t)sj << 6) + (lane << 1)]);
                    }
                    #pragma unroll
                    for (int u = 0; u < 8; u++) {
                        float2 f = __half22float2(hv[u]);
                        accx = fmaf(aj[u], f.x, accx);
                        accy = fmaf(aj[u], f.y, accy);
                    }
                }
                for (; jj < cnt; jj++) {
                    int   sj = __shfl_sync(0xffffffffu, s4[m], jj);
                    float a2 = __shfl_sync(0xffffffffu, al4[m], jj);
                    float2 f = __half22float2(*reinterpret_cast<const __half2*>(
                        &hh_in[((size_t)sj << 6) + (lane << 1)]));
                    accx = fmaf(a2, f.x, accx);
                    accy = fmaf(a2, f.y, accy);
                }
                float inv = 1.f / (ssum + 1e-16f);
                ox = accx * inv;
                oy = accy * inv;
            } else {
                agg_node<8>(n, lane, c, hh_in, asrc_in, adv[m], ox, oy);
            }
        }
        ox = fmaxf(ox + b0v, 0.f);
        oy = fmaxf(oy + b1v, 0.f);
        *reinterpret_cast<__half2*>(&As[r * LDA + (lane << 1)]) =
            __floats2half2_rn(ox, oy);
    }
    __syncthreads();

    // ---- 64x64 HMMA ----
    int rt = w >> 2, ct = w & 3;
    wmma::fragment<wmma::accumulator, 16, 16, 16, float> acc;
    wmma::fill_fragment(acc, 0.f);
    #pragma unroll
    for (int kt = 0; kt < HID / 16; kt++) {
        wmma::fragment<wmma::matrix_a, 16, 16, 16, __half, wmma::row_major> af;
        wmma::fragment<wmma::matrix_b, 16, 16, 16, __half, wmma::row_major> bf;
        wmma::load_matrix_sync(af, &As[(rt * 16) * LDA + kt * 16], LDA);
        wmma::load_matrix_sync(bf, &Bs[(kt * 16) * LDB + ct * 16], LDB);
        wmma::mma_sync(acc, af, bf, acc);
    }
    __syncthreads();
    wmma::store_matrix_sync(&Cs[(rt * 16) * LDC + ct * 16], acc, LDC,
                            wmma::mem_row_major);
    __syncthreads();

    // ---- epilogue: h fp16 + logits ----
    {
        int r = t >> 3;
        int n = n0 + r;
        int cbase = (t & 7) * 8;
        float s = 0.f, d = 0.f;
        if (n < NN) {
            #pragma unroll
            for (int cc = 0; cc < 8; cc += 2) {
                int col = cbase + cc;
                float v0 = Cs[r * LDC + col];
                float v1 = Cs[r * LDC + col + 1];
                *reinterpret_cast<__half2*>(&hh_out[((size_t)n << 6) + col]) =
                    __floats2half2_rn(v0, v1);
                s = fmaf(v0, as_[col], s); s = fmaf(v1, as_[col + 1], s);
                d = fmaf(v0, ad_[col], d); d = fmaf(v1, ad_[col + 1], d);
            }
        }
        #pragma unroll
        for (int off = 4; off > 0; off >>= 1) {
            s += __shfl_down_sync(0xffffffffu, s, off, 8);
            d += __shfl_down_sync(0xffffffffu, d, off, 8);
        }
        if ((t & 7) == 0 && n < NN) {
            asrc_out[n] = s;
            adst_out[n] = d;
        }
    }
}

// ---------------- final agg (layer 2) + pooling ----------------
__global__ void k_aggp(const int* __restrict__ batch,
                       const float* __restrict__ bias_last) {
    int n = blockIdx.x * 8 + (threadIdx.x >> 5);
    int lane = threadIdx.x & 31;
    float c = g_scal[3];
    float ox, oy;
    agg_node<8>(n, lane, c, g_hhA, g_asrcA, g_adstA[n], ox, oy);
    int g = batch[n];
    float2 bb = *reinterpret_cast<const float2*>(&bias_last[lane << 1]);
    float* p = &g_pooled[((size_t)g << 6) + (lane << 1)];
    asm volatile("red.global.add.v2.f32 [%0], {%1,%2};"
                 :: "l"(p), "f"(ox + bb.x), "f"(oy + bb.y) : "memory");
    if (lane == 0) atomicAdd(&g_gcnt[g], 1.f);
}

// ---------------- readout ----------------
__global__ void k_read(const float* __restrict__ lin_w,
                       const float* __restrict__ lin_b, float* __restrict__ outp) {
    __shared__ float r[64];
    int g = blockIdx.x, j = threadIdx.x;
    float cnt = fmaxf(g_gcnt[g], 1.f);
    r[j] = (g_pooled[(size_t)g * HID + j] / cnt) * lin_w[j];
    __syncthreads();
    for (int off = 32; off > 0; off >>= 1) {
        if (j < off) r[j] += r[j + off];
        __syncthreads();
    }
    if (j == 0) {
        float v = r[0] + lin_b[0];
        outp[g] = 1.f / (1.f + expf(-v));
    }
}

// ---------------- stream/event resources (static init) ----------------
static cudaStream_t g_stream2;
static cudaEvent_t  g_evFork, g_evGemm1, g_evPre;
namespace {
struct InitRes {
    InitRes() {
        cudaStreamCreateWithFlags(&g_stream2, cudaStreamNonBlocking);
        cudaEventCreateWithFlags(&g_evFork,  cudaEventDisableTiming);
        cudaEventCreateWithFlags(&g_evGemm1, cudaEventDisableTiming);
        cudaEventCreateWithFlags(&g_evPre,   cudaEventDisableTiming);
    }
};
InitRes g_initres;
}

// ---------------- launch ----------------
extern "C" void kernel_launch(void* const* d_in, const int* in_sizes, int n_in,
                              void* d_out, int out_size) {
    const float* x     = (const float*)d_in[0];
    const int*   eidx  = (const int*)  d_in[1];
    const float* ew    = (const float*)d_in[2];
    const int*   batch = (const int*)  d_in[3];
    const float* W[3]  = {(const float*)d_in[4],  (const float*)d_in[10], (const float*)d_in[16]};
    const float* as_[3]= {(const float*)d_in[5],  (const float*)d_in[11], (const float*)d_in[17]};
    const float* ad_[3]= {(const float*)d_in[6],  (const float*)d_in[12], (const float*)d_in[18]};
    const float* We[3] = {(const float*)d_in[7],  (const float*)d_in[13], (const float*)d_in[19]};
    const float* ae[3] = {(const float*)d_in[8],  (const float*)d_in[14], (const float*)d_in[20]};
    const float* b[3]  = {(const float*)d_in[9],  (const float*)d_in[15], (const float*)d_in[21]};
    const float* lin_w = (const float*)d_in[22];
    const float* lin_b = (const float*)d_in[23];
    float* outp = (float*)d_out;

    const int TILE_BLOCKS = (NN + 63) / 64;   // 782
    const int WARP_BLOCKS = NN / 8;           // 6250

    __half *hhA = nullptr, *hhB = nullptr;
    float *asA = nullptr, *asB = nullptr, *adA = nullptr, *adB = nullptr;
    cudaGetSymbolAddress((void**)&hhA, g_hhA);
    cudaGetSymbolAddress((void**)&hhB, g_hhB);
    cudaGetSymbolAddress((void**)&asA, g_asrcA);
    cudaGetSymbolAddress((void**)&asB, g_asrcB);
    cudaGetSymbolAddress((void**)&adA, g_adstA);
    cudaGetSymbolAddress((void**)&adB, g_adstB);

    // fork stream2: pre first (unblocks scan), then gemm1
    cudaEventRecord(g_evFork, 0);
    cudaStreamWaitEvent(g_stream2, g_evFork, 0);
    k_pre<<<PRE_BLOCKS, 256, 0, g_stream2>>>(We[0], ae[0], We[1], ae[1],
                                             We[2], ae[2], ew);
    cudaEventRecord(g_evPre, g_stream2);
    k_gemm1<<<TILE_BLOCKS, 128, 0, g_stream2>>>(x, W[0], as_[0], ad_[0]);
    cudaEventRecord(g_evGemm1, g_stream2);

    // capture stream: hist immediately, then scan (needs pre), scat
    k_hist<<<(NE / 4 + 255) / 256, 256>>>(eidx);
    cudaStreamWaitEvent(0, g_evPre, 0);
    k_s12<<<NCHUNK, 256>>>();
    k_scat<<<(ET + 255) / 256, 256>>>(eidx, ew);

    cudaStreamWaitEvent(0, g_evGemm1, 0);
    k_agge<<<TILE_BLOCKS, 512>>>(0, hhA, asA, adA, hhB, asB, adB,
                                 W[1], b[0], as_[1], ad_[1]);
    k_agge<<<TILE_BLOCKS, 512>>>(1, hhB, asB, adB, hhA, asA, adA,
                                 W[2], b[1], as_[2], ad_[2]);
    k_aggp<<<WARP_BLOCKS, 256>>>(batch, b[2]);
    k_read<<<NG, 64>>>(lin_w, lin_b, outp);
}

// round 14
// speedup vs baseline: 1.0929x; 1.0612x over previous
#include <cuda_runtime.h>
#include <cuda_fp16.h>
#include <mma.h>
#include <math.h>

using namespace nvcuda;

#define NN   50000
#define NE   800000
#define ET   850000
#define FIN  128
#define HID  64
#define NG   512
#define SLOPE 0.2f
#define PRE_BLOCKS 512
#define NCHUNK 196   // ceil(NN/256)

// ---------------- scratch ----------------
__device__ __half g_hhA[NN * HID];
__device__ __half g_hhB[NN * HID];
__device__ float g_asrcA[NN], g_asrcB[NN];
__device__ float g_adstA[NN], g_adstB[NN];
__device__ int   g_cnt[NN];           // ZERO at rest; s12 resets after use
__device__ int   g_rofs[NN];
__device__ int   g_pos[NN];
__device__ unsigned g_edge[ET];       // src u16 | eatt fp16
__device__ float g_pooled[NG * HID];
__device__ float g_gcnt[NG];
__device__ float g_scal[8];
__device__ int   g_bsum[256];
__device__ int   g_bpre[256];
__device__ float g_part[PRE_BLOCKS];
__device__ unsigned g_s1done;

// ---------------- k_pre ----------------
__global__ void k_pre(const float* __restrict__ We0, const float* __restrict__ ae0,
                      const float* __restrict__ We1, const float* __restrict__ ae1,
                      const float* __restrict__ We2, const float* __restrict__ ae2,
                      const float* __restrict__ ew) {
    __shared__ float sm[256];
    int b = blockIdx.x, t = threadIdx.x;
    int i = b * 256 + t;
    if (i < NG * HID) g_pooled[i] = 0.f;
    if (i < NG) g_gcnt[i] = 0.f;

    float acc = 0.f;
    for (int idx = i; idx < NE; idx += PRE_BLOCKS * 256) acc += ew[idx];
    sm[t] = acc;
    __syncthreads();
    for (int off = 128; off > 0; off >>= 1) {
        if (t < off) sm[t] += sm[t + off];
        __syncthreads();
    }
    if (t == 0) g_part[b] = sm[0];
    __syncthreads();

    if (b < 3) {
        const float* We = (b == 0) ? We0 : (b == 1) ? We1 : We2;
        const float* ae = (b == 0) ? ae0 : (b == 1) ? ae1 : ae2;
        sm[t] = (t < HID) ? We[t] * ae[t] : 0.f;
        __syncthreads();
        for (int off = 128; off > 0; off >>= 1) {
            if (t < off) sm[t] += sm[t + off];
            __syncthreads();
        }
        if (t == 0) g_scal[1 + b] = sm[0];
    }
}

__global__ void k_hist(const int* __restrict__ eidx) {
    int q = blockIdx.x * blockDim.x + threadIdx.x;
    if (q >= NE / 4) return;
    int4 d4 = reinterpret_cast<const int4*>(eidx + NE)[q];
    atomicAdd(&g_cnt[d4.x], 1);
    atomicAdd(&g_cnt[d4.y], 1);
    atomicAdd(&g_cnt[d4.z], 1);
    atomicAdd(&g_cnt[d4.w], 1);
}

// warp-shuffle 256-scan helper: INCLUSIVE scan across the block.
__device__ __forceinline__ int block_incl_scan256(int v, int t, int* wsum) {
    int lane = t & 31, w = t >> 5;
    int x = v;
    #pragma unroll
    for (int off = 1; off < 32; off <<= 1) {
        int y = __shfl_up_sync(0xffffffffu, x, off);
        if (lane >= off) x += y;
    }
    if (lane == 31) wsum[w] = x;
    __syncthreads();
    if (w == 0) {
        int s = (lane < 8) ? wsum[lane] : 0;
        #pragma unroll
        for (int off = 1; off < 8; off <<= 1) {
            int y = __shfl_up_sync(0xffffffffu, s, off);
            if (lane >= off) s += y;
        }
        if (lane < 8) wsum[lane] = s;
    }
    __syncthreads();
    if (w > 0) x += wsum[w - 1];
    return x;
}

// fused local scans + last-block global scan + ew total. Grid MUST be NCHUNK.
__global__ void k_s12() {
    __shared__ int wsum[8];
    __shared__ int s_last;
    int t = threadIdx.x;
    int i = blockIdx.x * 256 + t;
    int v = 0;
    if (i < NN) {
        v = g_cnt[i] + 1;      // fold self-loop
        g_cnt[i] = 0;          // reset for next replay
    }
    int incl = block_incl_scan256(v, t, wsum);
    if (i < NN) {
        int r = incl - v;
        g_rofs[i] = r;
        g_pos[i] = r;
    }
    if (t == 255) g_bsum[blockIdx.x] = incl;
    __threadfence();
    __syncthreads();
    if (t == 0) {
        unsigned done = atomicAdd(&g_s1done, 1u);
        s_last = (done == (unsigned)gridDim.x - 1u);
    }
    __syncthreads();
    if (!s_last) return;

    if (t == 0) g_s1done = 0;
    __syncthreads();
    int bv = (t < NCHUNK) ? g_bsum[t] : 0;
    int bincl = block_incl_scan256(bv, t, wsum);
    if (t < NCHUNK) g_bpre[t] = bincl - bv;
    __syncthreads();
    __shared__ float sf[256];
    sf[t] = g_part[t] + g_part[t + 256];
    __syncthreads();
    for (int off = 128; off > 0; off >>= 1) {
        if (t < off) sf[t] += sf[t + off];
        __syncthreads();
    }
    if (t == 0) g_scal[0] = sf[0];
}

__global__ void k_scat(const int* __restrict__ eidx, const float* __restrict__ ew) {
    int e = blockIdx.x * blockDim.x + threadIdx.x;
    if (e >= ET) return;
    int s, d;
    float a;
    if (e < NE) {
        s = eidx[e];
        d = eidx[NE + e];
        a = ew[e];
    } else {
        s = d = e - NE;
        a = g_scal[0] * (1.0f / (float)NE);
    }
    int p = atomicAdd(&g_pos[d], 1) + g_bpre[d >> 8];
    g_edge[p] = (unsigned)s |
                ((unsigned)__half_as_ushort(__float2half_rn(a)) << 16);
}

// ---------------- per-warp segment aggregation core ----------
template <int U>
__device__ __forceinline__ void agg_node(int n, int lane, float c,
                                         const __half* __restrict__ hh_in,
                                         const float* __restrict__ asrc_in,
                                         float adstn,
                                         float& ox, float& oy) {
    int start = g_rofs[n] + g_bpre[n >> 8];
    int n2 = n + 1;
    int end = (n2 == NN) ? ET : g_rofs[n2] + g_bpre[n2 >> 8];
    float accx = 0.f, accy = 0.f, ssum = 0.f;

    for (int base = start; base < end; base += 32) {
        int i = base + lane;
        int s_l = 0;
        float alpha = 0.f;
        if (i < end) {
            unsigned ev = g_edge[i];
            s_l = (int)(ev & 0xFFFFu);
            float ea = __half2float(__ushort_as_half((unsigned short)(ev >> 16)));
            float al = asrc_in[s_l] + adstn + ea * c;
            al = fmaxf(al, 0.f) + SLOPE * fminf(al, 0.f);
            alpha = __expf(al);
        }
        ssum += alpha;
        int cnt = min(32, end - base);
        int jj = 0;
        for (; jj + U <= cnt; jj += U) {
            __half2 hv[U];
            float aj[U];
            #pragma unroll
            for (int u = 0; u < U; u++) {
                int sj = __shfl_sync(0xffffffffu, s_l, jj + u);
                aj[u]  = __shfl_sync(0xffffffffu, alpha, jj + u);
                hv[u] = *reinterpret_cast<const __half2*>(
                    &hh_in[((size_t)sj << 6) + (lane << 1)]);
            }
            #pragma unroll
            for (int u = 0; u < U; u++) {
                float2 f = __half22float2(hv[u]);
                accx = fmaf(aj[u], f.x, accx);
                accy = fmaf(aj[u], f.y, accy);
            }
        }
        for (; jj < cnt; jj++) {
            int   sj = __shfl_sync(0xffffffffu, s_l, jj);
            float a2 = __shfl_sync(0xffffffffu, alpha, jj);
            float2 f = __half22float2(*reinterpret_cast<const __half2*>(
                &hh_in[((size_t)sj << 6) + (lane << 1)]));
            accx = fmaf(a2, f.x, accx);
            accy = fmaf(a2, f.y, accy);
        }
    }
    #pragma unroll
    for (int off = 16; off > 0; off >>= 1)
        ssum += __shfl_xor_sync(0xffffffffu, ssum, off);
    float inv = 1.f / (ssum + 1e-16f);
    ox = accx * inv;
    oy = accy * inv;
}

// ---------------- layer-1 GEMM (ext input) + logits -> A set ----------------
#define LDA 136
#define LDB 72
#define LDC 68

__global__ void k_gemm1(const float* __restrict__ X, const float* __restrict__ W,
                        const float* __restrict__ as_, const float* __restrict__ ad_) {
    __shared__ __align__(16) char sbuf[18432 + 17408];
    __half* Bs = reinterpret_cast<__half*>(sbuf);
    __half* As = reinterpret_cast<__half*>(sbuf + 18432);
    float*  Cs = reinterpret_cast<float*>(sbuf + 18432);

    int t = threadIdx.x;
    int w = t >> 5;
    int n0 = blockIdx.x * 64;

    {
        int r = t >> 1;
        int n = n0 + r;
        const float4* xrow = reinterpret_cast<const float4*>(X + (size_t)n * FIN);
        #pragma unroll
        for (int f = 0; f < 16; f++) {
            int c4 = (t & 1) * 16 + f;
            float4 v = (n < NN) ? xrow[c4] : make_float4(0, 0, 0, 0);
            __half2* p = reinterpret_cast<__half2*>(&As[r * LDA + c4 * 4]);
            p[0] = __floats2half2_rn(v.x, v.y);
            p[1] = __floats2half2_rn(v.z, v.w);
        }
        const float4* w4 = reinterpret_cast<const float4*>(W);
        for (int idx = t; idx < FIN * HID / 4; idx += 128) {
            int rr = idx >> 4, c4 = idx & 15;
            float4 v = w4[idx];
            __half2* p = reinterpret_cast<__half2*>(&Bs[rr * LDB + c4 * 4]);
            p[0] = __floats2half2_rn(v.x, v.y);
            p[1] = __floats2half2_rn(v.z, v.w);
        }
    }
    __syncthreads();

    wmma::fragment<wmma::accumulator, 16, 16, 16, float> acc[4];
    #pragma unroll
    for (int nt = 0; nt < 4; nt++) wmma::fill_fragment(acc[nt], 0.f);
    for (int kt = 0; kt < FIN / 16; kt++) {
        wmma::fragment<wmma::matrix_a, 16, 16, 16, __half, wmma::row_major> af;
        wmma::load_matrix_sync(af, &As[(w * 16) * LDA + kt * 16], LDA);
        #pragma unroll
        for (int nt = 0; nt < 4; nt++) {
            wmma::fragment<wmma::matrix_b, 16, 16, 16, __half, wmma::row_major> bf;
            wmma::load_matrix_sync(bf, &Bs[(kt * 16) * LDB + nt * 16], LDB);
            wmma::mma_sync(acc[nt], af, bf, acc[nt]);
        }
    }
    __syncthreads();
    #pragma unroll
    for (int nt = 0; nt < 4; nt++)
        wmma::store_matrix_sync(&Cs[(w * 16) * LDC + nt * 16], acc[nt], LDC,
                                wmma::mem_row_major);
    __syncthreads();

    {
        int r = t >> 1;
        int n = n0 + r;
        int cbase = (t & 1) * 32;
        float s = 0.f, d = 0.f;
        if (n < NN) {
            #pragma unroll
            for (int c = 0; c < 32; c += 2) {
                int col = cbase + c;
                float v0 = Cs[r * LDC + col];
                float v1 = Cs[r * LDC + col + 1];
                *reinterpret_cast<__half2*>(&g_hhA[((size_t)n << 6) + col]) =
                    __floats2half2_rn(v0, v1);
                s = fmaf(v0, as_[col], s); s = fmaf(v1, as_[col + 1], s);
                d = fmaf(v0, ad_[col], d); d = fmaf(v1, ad_[col + 1], d);
            }
        }
        s += __shfl_xor_sync(0xffffffffu, s, 1);
        d += __shfl_xor_sync(0xffffffffu, d, 1);
        if ((t & 1) == 0 && n < NN) {
            g_asrcA[n] = s;
            g_adstA[n] = d;
        }
    }
}

// ---------------- FUSED agg + GEMM (HID->HID) + logits, 32-node tile ----------
// 512 threads = 16 warps; warp w aggregates nodes n0+2w, n0+2w+1 (serial
// depth 2 instead of 4). MMA: 32x64 output = 8 16x16 tiles (warps 0-7).
__global__ void __launch_bounds__(512) k_agge(
    int layer,
    const __half* __restrict__ hh_in, const float* __restrict__ asrc_in,
    const float* __restrict__ adst_in,
    __half* __restrict__ hh_out, float* __restrict__ asrc_out,
    float* __restrict__ adst_out,
    const float* __restrict__ W, const float* __restrict__ bias_prev,
    const float* __restrict__ as_, const float* __restrict__ ad_) {
    __shared__ __align__(16) char sbuf[9216 + 8704];    // Bs[64][72] + As[32][136]
    __half* Bs = reinterpret_cast<__half*>(sbuf);
    __half* As = reinterpret_cast<__half*>(sbuf + 9216);
    float*  Cs = reinterpret_cast<float*>(sbuf + 9216); // [32][68] alias

    int t = threadIdx.x;
    int w = t >> 5;
    int lane = t & 31;
    int n0 = blockIdx.x * 32;
    float c = g_scal[1 + layer];
    float b0v = bias_prev[lane << 1];
    float b1v = bias_prev[(lane << 1) + 1];

    {
        const float4* w4 = reinterpret_cast<const float4*>(W);
        for (int idx = t; idx < HID * HID / 4; idx += 512) {
            int rr = idx >> 4, c4 = idx & 15;
            float4 v = w4[idx];
            __half2* p = reinterpret_cast<__half2*>(&Bs[rr * LDB + c4 * 4]);
            p[0] = __floats2half2_rn(v.x, v.y);
            p[1] = __floats2half2_rn(v.z, v.w);
        }
    }

    // ---- aggregate 2 nodes per warp into As ----
    #pragma unroll
    for (int m = 0; m < 2; m++) {
        int r = w * 2 + m;
        int n = n0 + r;
        float ox = 0.f, oy = 0.f;
        if (n < NN)
            agg_node<8>(n, lane, c, hh_in, asrc_in, adst_in[n], ox, oy);
        ox = fmaxf(ox + b0v, 0.f);
        oy = fmaxf(oy + b1v, 0.f);
        *reinterpret_cast<__half2*>(&As[r * LDA + (lane << 1)]) =
            __floats2half2_rn(ox, oy);
    }
    __syncthreads();

    // ---- 32x64 HMMA: warps 0-7, tile (rt, ct), rt in {0,1}, ct in {0..3} ----
    if (w < 8) {
        int rt = w >> 2, ct = w & 3;
        wmma::fragment<wmma::accumulator, 16, 16, 16, float> acc;
        wmma::fill_fragment(acc, 0.f);
        #pragma unroll
        for (int kt = 0; kt < HID / 16; kt++) {
            wmma::fragment<wmma::matrix_a, 16, 16, 16, __half, wmma::row_major> af;
            wmma::fragment<wmma::matrix_b, 16, 16, 16, __half, wmma::row_major> bf;
            wmma::load_matrix_sync(af, &As[(rt * 16) * LDA + kt * 16], LDA);
            wmma::load_matrix_sync(bf, &Bs[(kt * 16) * LDB + ct * 16], LDB);
            wmma::mma_sync(acc, af, bf, acc);
        }
        __syncthreads();
        wmma::store_matrix_sync(&Cs[(rt * 16) * LDC + ct * 16], acc, LDC,
                                wmma::mem_row_major);
    } else {
        __syncthreads();
    }
    __syncthreads();

    // ---- epilogue: 16 threads per row, 4 cols each ----
    {
        int r = t >> 4;                 // 0..31
        int n = n0 + r;
        int cbase = (t & 15) * 4;
        float s = 0.f, d = 0.f;
        if (n < NN) {
            #pragma unroll
            for (int cc = 0; cc < 4; cc += 2) {
                int col = cbase + cc;
                float v0 = Cs[r * LDC + col];
                float v1 = Cs[r * LDC + col + 1];
                *reinterpret_cast<__half2*>(&hh_out[((size_t)n << 6) + col]) =
                    __floats2half2_rn(v0, v1);
                s = fmaf(v0, as_[col], s); s = fmaf(v1, as_[col + 1], s);
                d = fmaf(v0, ad_[col], d); d = fmaf(v1, ad_[col + 1], d);
            }
        }
        #pragma unroll
        for (int off = 8; off > 0; off >>= 1) {
            s += __shfl_down_sync(0xffffffffu, s, off, 16);
            d += __shfl_down_sync(0xffffffffu, d, off, 16);
        }
        if ((t & 15) == 0 && n < NN) {
            asrc_out[n] = s;
            adst_out[n] = d;
        }
    }
}

// ---------------- final agg (layer 2) + pooling ----------------
__global__ void k_aggp(const int* __restrict__ batch,
                       const float* __restrict__ bias_last) {
    int n = blockIdx.x * 8 + (threadIdx.x >> 5);
    int lane = threadIdx.x & 31;
    float c = g_scal[3];
    float ox, oy;
    agg_node<8>(n, lane, c, g_hhA, g_asrcA, g_adstA[n], ox, oy);
    int g = batch[n];
    float2 bb = *reinterpret_cast<const float2*>(&bias_last[lane << 1]);
    float* p = &g_pooled[((size_t)g << 6) + (lane << 1)];
    asm volatile("red.global.add.v2.f32 [%0], {%1,%2};"
                 :: "l"(p), "f"(ox + bb.x), "f"(oy + bb.y) : "memory");
    if (lane == 0) atomicAdd(&g_gcnt[g], 1.f);
}

// ---------------- readout ----------------
__global__ void k_read(const float* __restrict__ lin_w,
                       const float* __restrict__ lin_b, float* __restrict__ outp) {
    __shared__ float r[64];
    int g = blockIdx.x, j = threadIdx.x;
    float cnt = fmaxf(g_gcnt[g], 1.f);
    r[j] = (g_pooled[(size_t)g * HID + j] / cnt) * lin_w[j];
    __syncthreads();
    for (int off = 32; off > 0; off >>= 1) {
        if (j < off) r[j] += r[j + off];
        __syncthreads();
    }
    if (j == 0) {
        float v = r[0] + lin_b[0];
        outp[g] = 1.f / (1.f + expf(-v));
    }
}

// ---------------- stream/event resources (static init) ----------------
static cudaStream_t g_stream2;
static cudaEvent_t  g_evFork, g_evGemm1, g_evPre;
namespace {
struct InitRes {
    InitRes() {
        cudaStreamCreateWithFlags(&g_stream2, cudaStreamNonBlocking);
        cudaEventCreateWithFlags(&g_evFork,  cudaEventDisableTiming);
        cudaEventCreateWithFlags(&g_evGemm1, cudaEventDisableTiming);
        cudaEventCreateWithFlags(&g_evPre,   cudaEventDisableTiming);
    }
};
InitRes g_initres;
}

// ---------------- launch ----------------
extern "C" void kernel_launch(void* const* d_in, const int* in_sizes, int n_in,
                              void* d_out, int out_size) {
    const float* x     = (const float*)d_in[0];
    const int*   eidx  = (const int*)  d_in[1];
    const float* ew    = (const float*)d_in[2];
    const int*   batch = (const int*)  d_in[3];
    const float* W[3]  = {(const float*)d_in[4],  (const float*)d_in[10], (const float*)d_in[16]};
    const float* as_[3]= {(const float*)d_in[5],  (const float*)d_in[11], (const float*)d_in[17]};
    const float* ad_[3]= {(const float*)d_in[6],  (const float*)d_in[12], (const float*)d_in[18]};
    const float* We[3] = {(const float*)d_in[7],  (const float*)d_in[13], (const float*)d_in[19]};
    const float* ae[3] = {(const float*)d_in[8],  (const float*)d_in[14], (const float*)d_in[20]};
    const float* b[3]  = {(const float*)d_in[9],  (const float*)d_in[15], (const float*)d_in[21]};
    const float* lin_w = (const float*)d_in[22];
    const float* lin_b = (const float*)d_in[23];
    float* outp = (float*)d_out;

    const int G1_BLOCKS  = (NN + 63) / 64;    // 782 (layer-1 gemm, 64-node tile)
    const int FUSE_BLOCKS = (NN + 31) / 32;   // 1563 (fused agg+gemm, 32-node tile)
    const int WARP_BLOCKS = NN / 8;           // 6250

    __half *hhA = nullptr, *hhB = nullptr;
    float *asA = nullptr, *asB = nullptr, *adA = nullptr, *adB = nullptr;
    cudaGetSymbolAddress((void**)&hhA, g_hhA);
    cudaGetSymbolAddress((void**)&hhB, g_hhB);
    cudaGetSymbolAddress((void**)&asA, g_asrcA);
    cudaGetSymbolAddress((void**)&asB, g_asrcB);
    cudaGetSymbolAddress((void**)&adA, g_adstA);
    cudaGetSymbolAddress((void**)&adB, g_adstB);

    // fork stream2: pre first (unblocks scan), then gemm1
    cudaEventRecord(g_evFork, 0);
    cudaStreamWaitEvent(g_stream2, g_evFork, 0);
    k_pre<<<PRE_BLOCKS, 256, 0, g_stream2>>>(We[0], ae[0], We[1], ae[1],
                                             We[2], ae[2], ew);
    cudaEventRecord(g_evPre, g_stream2);
    k_gemm1<<<G1_BLOCKS, 128, 0, g_stream2>>>(x, W[0], as_[0], ad_[0]);
    cudaEventRecord(g_evGemm1, g_stream2);

    // capture stream: hist immediately, then scan (needs pre), scat
    k_hist<<<(NE / 4 + 255) / 256, 256>>>(eidx);
    cudaStreamWaitEvent(0, g_evPre, 0);
    k_s12<<<NCHUNK, 256>>>();
    k_scat<<<(ET + 255) / 256, 256>>>(eidx, ew);

    cudaStreamWaitEvent(0, g_evGemm1, 0);
    k_agge<<<FUSE_BLOCKS, 512>>>(0, hhA, asA, adA, hhB, asB, adB,
                                 W[1], b[0], as_[1], ad_[1]);
    k_agge<<<FUSE_BLOCKS, 512>>>(1, hhB, asB, adB, hhA, asA, adA,
                                 W[2], b[1], as_[2], ad_[2]);
    k_aggp<<<WARP_BLOCKS, 256>>>(batch, b[2]);
    k_read<<<NG, 64>>>(lin_w, lin_b, outp);
}